// round 1
// baseline (speedup 1.0000x reference)
#include <cuda_runtime.h>

// NetVLAD fused kernel, fp32 scalar v1.
// x:[N,C,H,W] fp32, conv_w:[K,C], centroids:[K,C] -> out:[N, K*C] fp32
// N=64, C=128, H=W=64 (S=4096), K=64.

#define N_      64
#define C_      128
#define K_      64
#define S_      4096
#define SPLITS  8
#define S_PER   (S_ / SPLITS)     // 512 pixels per CTA
#define TILE_P  64
#define TILES   (S_PER / TILE_P)  // 8
#define TPB     256

#define WT_STRIDE 68    // conv_w^T  [C][K]  padded
#define XS_STRIDE 68    // x tile    [C][P]  padded
#define XT_STRIDE 132   // x tile^T  [P][C]  padded
#define LS_STRIDE 68    // logits/a  [P][K]  padded

// Per-split partial accumulators (no atomics; reduced by finalize kernel).
__device__ float g_vlad_part[SPLITS * N_ * K_ * C_];   // 16 MiB
__device__ float g_asum_part[SPLITS * N_ * K_];

__global__ void __launch_bounds__(TPB)
netvlad_main(const float* __restrict__ x, const float* __restrict__ conv_w) {
    extern __shared__ float smem[];
    float* wT     = smem;                         // [C_][WT_STRIDE]
    float* xs     = wT + C_ * WT_STRIDE;          // [C_][XS_STRIDE]
    float* xT     = xs + C_ * XS_STRIDE;          // [TILE_P][XT_STRIDE]
    float* ls     = xT + TILE_P * XT_STRIDE;      // [TILE_P][LS_STRIDE]
    float* asum_s = ls + TILE_P * LS_STRIDE;      // [K_]

    const int tid   = threadIdx.x;
    const int split = blockIdx.x;
    const int n     = blockIdx.y;
    const float* xg = x + (size_t)n * C_ * S_ + split * S_PER;

    // conv_w [K][C] -> wT [C][K] (coalesced gmem read)
    for (int i = tid; i < K_ * C_; i += TPB) {
        int k = i >> 7, c = i & 127;
        wT[c * WT_STRIDE + k] = conv_w[i];
    }
    if (tid < K_) asum_s[tid] = 0.f;

    const int ty = tid >> 4, tx = tid & 15;
    const int k0  = ty * 4;   // 4 clusters per thread (both GEMMs)
    const int p0  = tx * 4;   // 4 pixels per thread (logits GEMM)
    const int c0v = tx * 8;   // 8 channels per thread (vlad GEMM)

    float acc[4][8];          // vlad accumulator: (k0+i, c0v+j)
    #pragma unroll
    for (int i = 0; i < 4; i++)
        #pragma unroll
        for (int j = 0; j < 8; j++) acc[i][j] = 0.f;

    __syncthreads();

    for (int t = 0; t < TILES; ++t) {
        const int sbase = t * TILE_P;

        // ---- load x tile into both layouts ----
        for (int i = tid; i < C_ * TILE_P / 4; i += TPB) {
            int c  = i >> 4;
            int p4 = (i & 15) << 2;
            float4 v = *(const float4*)(xg + (size_t)c * S_ + sbase + p4);
            float* xr = xs + c * XS_STRIDE + p4;
            xr[0] = v.x; xr[1] = v.y; xr[2] = v.z; xr[3] = v.w;
            xT[(p4 + 0) * XT_STRIDE + c] = v.x;
            xT[(p4 + 1) * XT_STRIDE + c] = v.y;
            xT[(p4 + 2) * XT_STRIDE + c] = v.z;
            xT[(p4 + 3) * XT_STRIDE + c] = v.w;
        }
        __syncthreads();

        // ---- logits GEMM: L[k][p] = sum_c wT[c][k] * xs[c][p] ----
        float lg[4][4];
        #pragma unroll
        for (int i = 0; i < 4; i++)
            #pragma unroll
            for (int j = 0; j < 4; j++) lg[i][j] = 0.f;

        #pragma unroll 4
        for (int c = 0; c < C_; ++c) {
            float4 wv = *(const float4*)(wT + c * WT_STRIDE + k0);
            float4 xv = *(const float4*)(xs + c * XS_STRIDE + p0);
            const float w[4] = {wv.x, wv.y, wv.z, wv.w};
            const float xp[4] = {xv.x, xv.y, xv.z, xv.w};
            #pragma unroll
            for (int i = 0; i < 4; i++)
                #pragma unroll
                for (int j = 0; j < 4; j++)
                    lg[i][j] = fmaf(w[i], xp[j], lg[i][j]);
        }
        // store as ls[p][k]
        #pragma unroll
        for (int j = 0; j < 4; j++)
            *(float4*)(ls + (p0 + j) * LS_STRIDE + k0) =
                make_float4(lg[0][j], lg[1][j], lg[2][j], lg[3][j]);
        __syncthreads();

        // ---- softmax over K per pixel (64 threads, one per pixel) ----
        if (tid < TILE_P) {
            float* row = ls + tid * LS_STRIDE;
            float m = row[0];
            #pragma unroll
            for (int k = 1; k < K_; k++) m = fmaxf(m, row[k]);
            float ssum = 0.f;
            #pragma unroll
            for (int k = 0; k < K_; k++) {
                float e = __expf(row[k] - m);
                row[k] = e;
                ssum += e;
            }
            float inv = 1.f / ssum;
            #pragma unroll
            for (int k = 0; k < K_; k++) row[k] *= inv;
        }
        __syncthreads();

        // ---- asum[k] += sum_p a[p][k] ----
        if (tid < K_) {
            float s = 0.f;
            #pragma unroll 8
            for (int p = 0; p < TILE_P; p++) s += ls[p * LS_STRIDE + tid];
            asum_s[tid] += s;
        }

        // ---- vlad GEMM: acc[k][c] += sum_p a[p][k] * xT[p][c] ----
        #pragma unroll 2
        for (int p = 0; p < TILE_P; ++p) {
            float4 av = *(const float4*)(ls + p * LS_STRIDE + k0);
            float4 xa = *(const float4*)(xT + p * XT_STRIDE + c0v);
            float4 xb = *(const float4*)(xT + p * XT_STRIDE + c0v + 4);
            const float a[4]  = {av.x, av.y, av.z, av.w};
            const float xc[8] = {xa.x, xa.y, xa.z, xa.w, xb.x, xb.y, xb.z, xb.w};
            #pragma unroll
            for (int i = 0; i < 4; i++)
                #pragma unroll
                for (int j = 0; j < 8; j++)
                    acc[i][j] = fmaf(a[i], xc[j], acc[i][j]);
        }
        __syncthreads();
    }

    // ---- write partials ----
    float* outp = g_vlad_part + (size_t)(split * N_ + n) * K_ * C_;
    #pragma unroll
    for (int i = 0; i < 4; i++) {
        *(float4*)(outp + (k0 + i) * C_ + c0v) =
            make_float4(acc[i][0], acc[i][1], acc[i][2], acc[i][3]);
        *(float4*)(outp + (k0 + i) * C_ + c0v + 4) =
            make_float4(acc[i][4], acc[i][5], acc[i][6], acc[i][7]);
    }
    if (tid < K_) g_asum_part[(size_t)(split * N_ + n) * K_ + tid] = asum_s[tid];
}

__global__ void __launch_bounds__(TPB)
netvlad_finalize(const float* __restrict__ centroids, float* __restrict__ out) {
    __shared__ float v[K_ * C_];      // 32 KB
    __shared__ float asum_s[K_];
    __shared__ float rowinv[K_];
    __shared__ float wsum[TPB / 32];

    const int n = blockIdx.x;
    const int tid = threadIdx.x;
    const int warp = tid >> 5, lane = tid & 31;

    if (tid < K_) {
        float s = 0.f;
        #pragma unroll
        for (int sp = 0; sp < SPLITS; ++sp)
            s += g_asum_part[(size_t)(sp * N_ + n) * K_ + tid];
        asum_s[tid] = s;
    }
    __syncthreads();

    // reduce splits + subtract asum*centroid
    for (int idx = tid; idx < K_ * C_; idx += TPB) {
        int k = idx >> 7;
        float s = 0.f;
        #pragma unroll
        for (int sp = 0; sp < SPLITS; ++sp)
            s += g_vlad_part[(size_t)(sp * N_ + n) * (K_ * C_) + idx];
        s -= asum_s[k] * centroids[idx];
        v[idx] = s;
    }
    __syncthreads();

    // per-cluster L2 norm (warp per row, 8 rows per warp)
    for (int r = 0; r < 8; ++r) {
        int k = warp * 8 + r;
        const float* row = v + k * C_;
        float s = 0.f;
        #pragma unroll
        for (int c = lane; c < C_; c += 32) {
            float t = row[c];
            s += t * t;
        }
        #pragma unroll
        for (int o = 16; o; o >>= 1) s += __shfl_xor_sync(0xFFFFFFFFu, s, o);
        if (lane == 0) rowinv[k] = rsqrtf(s);
    }
    __syncthreads();

    // intra-normalize + global sumsq
    float local = 0.f;
    for (int idx = tid; idx < K_ * C_; idx += TPB) {
        int k = idx >> 7;
        float t = v[idx] * rowinv[k];
        v[idx] = t;
        local += t * t;
    }
    #pragma unroll
    for (int o = 16; o; o >>= 1) local += __shfl_xor_sync(0xFFFFFFFFu, local, o);
    if (lane == 0) wsum[warp] = local;
    __syncthreads();
    if (tid == 0) {
        float s = 0.f;
        #pragma unroll
        for (int w = 0; w < TPB / 32; w++) s += wsum[w];
        wsum[0] = rsqrtf(s);
    }
    __syncthreads();
    const float ginv = wsum[0];

    for (int idx = tid; idx < K_ * C_; idx += TPB)
        out[(size_t)n * (K_ * C_) + idx] = v[idx] * ginv;
}

extern "C" void kernel_launch(void* const* d_in, const int* in_sizes, int n_in,
                              void* d_out, int out_size) {
    const float* x         = (const float*)d_in[0];
    const float* conv_w    = (const float*)d_in[1];
    const float* centroids = (const float*)d_in[2];
    float* out = (float*)d_out;

    const size_t smem_bytes =
        (size_t)(C_ * WT_STRIDE + C_ * XS_STRIDE + TILE_P * XT_STRIDE +
                 TILE_P * LS_STRIDE + K_) * sizeof(float);   // ~118 KB

    cudaFuncSetAttribute(netvlad_main,
                         cudaFuncAttributeMaxDynamicSharedMemorySize,
                         (int)smem_bytes);

    netvlad_main<<<dim3(SPLITS, N_), TPB, smem_bytes>>>(x, conv_w);
    netvlad_finalize<<<N_, TPB>>>(centroids, out);
}

// round 3
// speedup vs baseline: 3.1139x; 3.1139x over previous
#include <cuda_runtime.h>
#include <cuda_bf16.h>
#include <cstdint>

// NetVLAD fused warp-MMA kernel (bf16 2-term split, fp32 accum, mma.sync HMMA).
// x:[64,128,64,64] fp32, conv_w:[64,128], centroids:[64,128] -> out:[64,8192] fp32

#define NB      64
#define CC      128
#define KK      64
#define SS      4096
#define SPLITS  2
#define SPER    (SS / SPLITS)   // 2048
#define TP      128             // pixels per tile
#define NTILES  (SPER / TP)     // 16
#define THREADS 256

// SMEM layout (dynamic): all rows swizzled SW128-style
#define OFF_XH   0        // x hi  [128 p][256 B]  (128 c bf16)
#define OFF_XL   32768    // x lo
#define OFF_WH   65536    // w hi  [64 k][256 B]
#define OFF_WL   81920
#define OFF_AH   98304    // a hi  [128 p][128 B]  (64 k bf16)
#define OFF_AL   114688
#define OFF_ASUM 131072   // 64 floats
#define SMEM_BYTES (OFF_ASUM + 256)

__device__ float g_vlad_part[SPLITS * NB * KK * CC];   // [split][n][k][c]
__device__ float g_asum_part[SPLITS * NB * KK];

__device__ __forceinline__ uint32_t smem_u32(const void* p) {
    uint32_t a;
    asm("{ .reg .u64 t; cvta.to.shared.u64 t, %1; cvt.u32.u64 %0, t; }" : "=r"(a) : "l"(p));
    return a;
}
__device__ __forceinline__ uint32_t swz256(int row, int byte) {
    return (uint32_t)(row * 256 + (byte ^ ((row & 7) << 4)));
}
__device__ __forceinline__ uint32_t swz128(int row, int byte) {
    return (uint32_t)(row * 128 + (byte ^ ((row & 7) << 4)));
}

#define LDSM_X4(R, addr) \
    asm volatile("ldmatrix.sync.aligned.m8n8.x4.shared.b16 {%0,%1,%2,%3}, [%4];" \
        : "=r"((R)[0]), "=r"((R)[1]), "=r"((R)[2]), "=r"((R)[3]) : "r"(addr))
#define LDSM_X4T(R, addr) \
    asm volatile("ldmatrix.sync.aligned.m8n8.x4.trans.shared.b16 {%0,%1,%2,%3}, [%4];" \
        : "=r"((R)[0]), "=r"((R)[1]), "=r"((R)[2]), "=r"((R)[3]) : "r"(addr))

__device__ __forceinline__ void mma16816(float* d, const uint32_t* a,
                                         uint32_t b0, uint32_t b1) {
    asm volatile(
        "mma.sync.aligned.m16n8k16.row.col.f32.bf16.bf16.f32 "
        "{%0,%1,%2,%3}, {%4,%5,%6,%7}, {%8,%9}, {%0,%1,%2,%3};"
        : "+f"(d[0]), "+f"(d[1]), "+f"(d[2]), "+f"(d[3])
        : "r"(a[0]), "r"(a[1]), "r"(a[2]), "r"(a[3]), "r"(b0), "r"(b1));
}

__device__ __forceinline__ void split_bf16(float v, uint16_t& h, uint16_t& l) {
    __nv_bfloat16 hb = __float2bfloat16_rn(v);
    __nv_bfloat16 lb = __float2bfloat16_rn(v - __bfloat162float(hb));
    h = __bfloat16_as_ushort(hb);
    l = __bfloat16_as_ushort(lb);
}

__global__ void __launch_bounds__(THREADS)
netvlad_mma(const float* __restrict__ x, const float* __restrict__ conv_w) {
    extern __shared__ char smem[];
    const uint32_t sb = smem_u32(smem);
    const int tid  = threadIdx.x;
    const int lane = tid & 31;
    const int warp = tid >> 5;
    const int split = blockIdx.x;
    const int n     = blockIdx.y;

    if (tid < KK) ((float*)(smem + OFF_ASUM))[tid] = 0.f;

    // conv_w [64][128] -> bf16 hi/lo, swizzled rows
    for (int i = tid; i < KK * CC; i += THREADS) {
        int k = i >> 7, c = i & 127;
        uint16_t h, l;
        split_bf16(conv_w[i], h, l);
        uint32_t o = swz256(k, c * 2);
        *(uint16_t*)(smem + OFF_WH + o) = h;
        *(uint16_t*)(smem + OFF_WL + o) = l;
    }

    float vacc[32];            // GEMM2 accumulator (persistent over tiles)
    #pragma unroll
    for (int i = 0; i < 32; i++) vacc[i] = 0.f;
    float asum[16];            // per-thread asum partials (k = nt*8+(lane&3)*2+{0,1})
    #pragma unroll
    for (int i = 0; i < 16; i++) asum[i] = 0.f;

    const float* xb = x + ((size_t)n * CC) * SS + (size_t)split * SPER;
    const int mt = warp & 3;   // GEMM2 m-tile (clusters)
    const int ch = warp >> 2;  // GEMM2 n-half (channels)
    const int wp = warp * 16;  // GEMM1 pixel base

    for (int t = 0; t < NTILES; ++t) {
        __syncthreads();  // prev-tile consumers done (also covers w-fill on t=0)

        // ---- load x tile [128 c][128 p], convert, store [p][c] hi/lo ----
        const float* xt = xb + t * TP;
        #pragma unroll
        for (int g = 0; g < 4; ++g) {
            float v[16];
            #pragma unroll
            for (int cc = 0; cc < 4; ++cc) {
                const float* row = xt + (size_t)(warp * 16 + g * 4 + cc) * SS;
                #pragma unroll
                for (int seg = 0; seg < 4; ++seg)
                    v[cc * 4 + seg] = row[seg * 32 + lane];
            }
            #pragma unroll
            for (int cc = 0; cc < 4; ++cc) {
                int c = warp * 16 + g * 4 + cc;
                #pragma unroll
                for (int seg = 0; seg < 4; ++seg) {
                    int p = seg * 32 + lane;
                    uint16_t h, l;
                    split_bf16(v[cc * 4 + seg], h, l);
                    uint32_t o = swz256(p, c * 2);
                    *(uint16_t*)(smem + OFF_XH + o) = h;
                    *(uint16_t*)(smem + OFF_XL + o) = l;
                }
            }
        }
        __syncthreads();

        // ---- GEMM1: logits[p][k] = x · w^T (3-way bf16 split) ----
        float lacc[32];
        #pragma unroll
        for (int i = 0; i < 32; i++) lacc[i] = 0.f;

        #pragma unroll
        for (int ks = 0; ks < 8; ++ks) {
            uint32_t ah[4], al[4];
            {
                int arow = wp + (lane & 15);
                int abyte = ks * 32 + (lane >> 4) * 16;
                LDSM_X4(ah, sb + OFF_XH + swz256(arow, abyte));
                LDSM_X4(al, sb + OFF_XL + swz256(arow, abyte));
            }
            uint32_t bh[16], bl[16];
            #pragma unroll
            for (int np = 0; np < 4; ++np) {
                int brow = np * 16 + (lane & 7) + ((lane >> 4) & 1) * 8;
                int bbyte = ks * 32 + ((lane >> 3) & 1) * 16;
                LDSM_X4(bh + np * 4, sb + OFF_WH + swz256(brow, bbyte));
                LDSM_X4(bl + np * 4, sb + OFF_WL + swz256(brow, bbyte));
            }
            #pragma unroll
            for (int nt = 0; nt < 8; ++nt) {
                int bi = (nt >> 1) * 4 + (nt & 1) * 2;
                mma16816(lacc + nt * 4, ah, bh[bi], bh[bi + 1]);
                mma16816(lacc + nt * 4, ah, bl[bi], bl[bi + 1]);
                mma16816(lacc + nt * 4, al, bh[bi], bh[bi + 1]);
            }
        }

        // ---- softmax over K (per pixel; quad holds 64 k across 4 lanes) ----
        float m1 = -1e30f, m2 = -1e30f;
        #pragma unroll
        for (int nt = 0; nt < 8; ++nt) {
            m1 = fmaxf(m1, fmaxf(lacc[nt * 4 + 0], lacc[nt * 4 + 1]));
            m2 = fmaxf(m2, fmaxf(lacc[nt * 4 + 2], lacc[nt * 4 + 3]));
        }
        #pragma unroll
        for (int o = 1; o <= 2; o <<= 1) {
            m1 = fmaxf(m1, __shfl_xor_sync(0xFFFFFFFFu, m1, o));
            m2 = fmaxf(m2, __shfl_xor_sync(0xFFFFFFFFu, m2, o));
        }
        float s1 = 0.f, s2 = 0.f;
        #pragma unroll
        for (int nt = 0; nt < 8; ++nt) {
            float e0 = __expf(lacc[nt * 4 + 0] - m1);
            float e1 = __expf(lacc[nt * 4 + 1] - m1);
            float e2 = __expf(lacc[nt * 4 + 2] - m2);
            float e3 = __expf(lacc[nt * 4 + 3] - m2);
            lacc[nt * 4 + 0] = e0; lacc[nt * 4 + 1] = e1;
            lacc[nt * 4 + 2] = e2; lacc[nt * 4 + 3] = e3;
            s1 += e0 + e1; s2 += e2 + e3;
        }
        #pragma unroll
        for (int o = 1; o <= 2; o <<= 1) {
            s1 += __shfl_xor_sync(0xFFFFFFFFu, s1, o);
            s2 += __shfl_xor_sync(0xFFFFFFFFu, s2, o);
        }
        const float i1 = 1.f / s1, i2 = 1.f / s2;

        // ---- a -> SMEM bf16 hi/lo, accumulate asum ----
        {
            int p1 = wp + (lane >> 2), p2 = p1 + 8;
            #pragma unroll
            for (int nt = 0; nt < 8; ++nt) {
                float a0 = lacc[nt * 4 + 0] * i1, a1 = lacc[nt * 4 + 1] * i1;
                float a2 = lacc[nt * 4 + 2] * i2, a3 = lacc[nt * 4 + 3] * i2;
                asum[nt * 2 + 0] += a0 + a2;
                asum[nt * 2 + 1] += a1 + a3;
                int kbyte = nt * 16 + (lane & 3) * 4;
                uint16_t h0, l0, h1, l1;
                split_bf16(a0, h0, l0); split_bf16(a1, h1, l1);
                *(uint32_t*)(smem + OFF_AH + swz128(p1, kbyte)) = (uint32_t)h0 | ((uint32_t)h1 << 16);
                *(uint32_t*)(smem + OFF_AL + swz128(p1, kbyte)) = (uint32_t)l0 | ((uint32_t)l1 << 16);
                split_bf16(a2, h0, l0); split_bf16(a3, h1, l1);
                *(uint32_t*)(smem + OFF_AH + swz128(p2, kbyte)) = (uint32_t)h0 | ((uint32_t)h1 << 16);
                *(uint32_t*)(smem + OFF_AL + swz128(p2, kbyte)) = (uint32_t)l0 | ((uint32_t)l1 << 16);
            }
        }
        __syncthreads();

        // ---- GEMM2: vlad^T[k][c] += a^T · x (3-way split; trans loads) ----
        #pragma unroll
        for (int ps = 0; ps < 8; ++ps) {
            uint32_t aah[4], aal[4];
            {
                int arow = ps * 16 + (lane & 7) + (lane >> 4) * 8;
                int abyte = mt * 32 + ((lane >> 3) & 1) * 16;
                LDSM_X4T(aah, sb + OFF_AH + swz128(arow, abyte));
                LDSM_X4T(aal, sb + OFF_AL + swz128(arow, abyte));
            }
            uint32_t bxh[16], bxl[16];
            #pragma unroll
            for (int np = 0; np < 4; ++np) {
                int brow = ps * 16 + (lane & 7) + ((lane >> 3) & 1) * 8;
                int bbyte = ch * 128 + np * 32 + (lane >> 4) * 16;
                LDSM_X4T(bxh + np * 4, sb + OFF_XH + swz256(brow, bbyte));
                LDSM_X4T(bxl + np * 4, sb + OFF_XL + swz256(brow, bbyte));
            }
            #pragma unroll
            for (int nt = 0; nt < 8; ++nt) {
                int bi = (nt >> 1) * 4 + (nt & 1) * 2;
                mma16816(vacc + nt * 4, aah, bxh[bi], bxh[bi + 1]);
                mma16816(vacc + nt * 4, aah, bxl[bi], bxl[bi + 1]);
                mma16816(vacc + nt * 4, aal, bxh[bi], bxh[bi + 1]);
            }
        }
    }

    // ---- write vlad partials [k][c] ----
    {
        float* dst = g_vlad_part + (size_t)(split * NB + n) * (KK * CC);
        int k1 = mt * 16 + (lane >> 2), k2 = k1 + 8;
        #pragma unroll
        for (int nt = 0; nt < 8; ++nt) {
            int c = ch * 64 + nt * 8 + (lane & 3) * 2;
            *(float2*)(dst + k1 * CC + c) = make_float2(vacc[nt * 4 + 0], vacc[nt * 4 + 1]);
            *(float2*)(dst + k2 * CC + c) = make_float2(vacc[nt * 4 + 2], vacc[nt * 4 + 3]);
        }
    }
    // ---- asum: warp reduce + smem atomic combine ----
    #pragma unroll
    for (int i = 0; i < 16; ++i) {
        float s = asum[i];
        s += __shfl_xor_sync(0xFFFFFFFFu, s, 4);
        s += __shfl_xor_sync(0xFFFFFFFFu, s, 8);
        s += __shfl_xor_sync(0xFFFFFFFFu, s, 16);
        asum[i] = s;
    }
    if (lane < 4) {
        float* as = (float*)(smem + OFF_ASUM);
        #pragma unroll
        for (int nt = 0; nt < 8; ++nt) {
            atomicAdd(as + nt * 8 + lane * 2 + 0, asum[nt * 2 + 0]);
            atomicAdd(as + nt * 8 + lane * 2 + 1, asum[nt * 2 + 1]);
        }
    }
    __syncthreads();
    if (tid < KK)
        g_asum_part[(size_t)(split * NB + n) * KK + tid] = ((float*)(smem + OFF_ASUM))[tid];
}

#define FTPB 512
__global__ void __launch_bounds__(FTPB)
netvlad_finalize(const float* __restrict__ centroids, float* __restrict__ out) {
    __shared__ float v[KK * CC];
    __shared__ float asum_s[KK];
    __shared__ float rowinv[KK];
    __shared__ float wsum[FTPB / 32];

    const int n = blockIdx.x;
    const int tid = threadIdx.x;
    const int warp = tid >> 5, lane = tid & 31;

    if (tid < KK)
        asum_s[tid] = g_asum_part[(size_t)n * KK + tid] +
                      g_asum_part[(size_t)(NB + n) * KK + tid];
    __syncthreads();

    const float* p0 = g_vlad_part + (size_t)n * (KK * CC);
    const float* p1 = g_vlad_part + (size_t)(NB + n) * (KK * CC);
    for (int idx = tid; idx < KK * CC; idx += FTPB) {
        int k = idx >> 7;
        v[idx] = p0[idx] + p1[idx] - asum_s[k] * centroids[idx];
    }
    __syncthreads();

    #pragma unroll
    for (int r = 0; r < 4; ++r) {
        int k = warp * 4 + r;
        const float* row = v + k * CC;
        float s = 0.f;
        #pragma unroll
        for (int c = lane; c < CC; c += 32) { float t = row[c]; s += t * t; }
        #pragma unroll
        for (int o = 16; o; o >>= 1) s += __shfl_xor_sync(0xFFFFFFFFu, s, o);
        if (lane == 0) rowinv[k] = rsqrtf(s);
    }
    __syncthreads();

    float local = 0.f;
    for (int idx = tid; idx < KK * CC; idx += FTPB) {
        float t = v[idx] * rowinv[idx >> 7];
        v[idx] = t;
        local += t * t;
    }
    #pragma unroll
    for (int o = 16; o; o >>= 1) local += __shfl_xor_sync(0xFFFFFFFFu, local, o);
    if (lane == 0) wsum[warp] = local;
    __syncthreads();
    if (tid == 0) {
        float s = 0.f;
        #pragma unroll
        for (int w = 0; w < FTPB / 32; ++w) s += wsum[w];
        wsum[0] = rsqrtf(s);
    }
    __syncthreads();
    const float ginv = wsum[0];

    for (int idx = tid; idx < KK * CC; idx += FTPB)
        out[(size_t)n * (KK * CC) + idx] = v[idx] * ginv;
}

extern "C" void kernel_launch(void* const* d_in, const int* in_sizes, int n_in,
                              void* d_out, int out_size) {
    const float* x         = (const float*)d_in[0];
    const float* conv_w    = (const float*)d_in[1];
    const float* centroids = (const float*)d_in[2];
    float* out = (float*)d_out;

    cudaFuncSetAttribute(netvlad_mma, cudaFuncAttributeMaxDynamicSharedMemorySize, SMEM_BYTES);
    netvlad_mma<<<dim3(SPLITS, NB), THREADS, SMEM_BYTES>>>(x, conv_w);
    netvlad_finalize<<<NB, FTPB>>>(centroids, out);
}

// round 4
// speedup vs baseline: 4.5313x; 1.4552x over previous
#include <cuda_runtime.h>
#include <cuda_bf16.h>
#include <cstdint>

// NetVLAD fused warp-MMA kernel v2: single bf16, cp.async pipeline, fused finalize.
// x:[64,128,64,64] fp32, conv_w:[64,128], centroids:[64,128] -> out:[64,8192] fp32

#define NB      64
#define CC      128
#define KK      64
#define SS      4096
#define SPLITS  2
#define SPER    (SS / SPLITS)   // 2048
#define TP      128             // pixels per tile
#define NTILES  (SPER / TP)     // 16
#define THREADS 256

// SMEM layout (bytes)
#define OFF_ST0  0               // fp32 staging tile A [128 c][512 B]
#define OFF_ST1  65536           // fp32 staging tile B
#define OFF_XB   131072          // x bf16 [128 p][256 B] swizzled
#define OFF_W    163840          // w bf16 [64 k][256 B] swizzled
#define OFF_A    180224          // a bf16 [128 p][128 B] swizzled
#define OFF_ASUM 196608          // 64 floats
#define SMEM_BYTES (OFF_ASUM + 256)

__device__ float g_vlad_part[SPLITS * NB * KK * CC];   // [split][n][k][c]
__device__ float g_asum_part[SPLITS * NB * KK];
__device__ unsigned int g_flag[NB];

__device__ __forceinline__ uint32_t smem_u32(const void* p) {
    uint32_t a;
    asm("{ .reg .u64 t; cvta.to.shared.u64 t, %1; cvt.u32.u64 %0, t; }" : "=r"(a) : "l"(p));
    return a;
}
__device__ __forceinline__ uint32_t swz256(int row, int byte) {
    return (uint32_t)(row * 256 + (byte ^ ((row & 7) << 4)));
}
__device__ __forceinline__ uint32_t swz128(int row, int byte) {
    return (uint32_t)(row * 128 + (byte ^ ((row & 7) << 4)));
}

#define CP_ASYNC16(dst, src) \
    asm volatile("cp.async.cg.shared.global [%0], [%1], 16;" :: "r"(dst), "l"(src))
#define CP_COMMIT() asm volatile("cp.async.commit_group;")
#define CP_WAIT(n)  asm volatile("cp.async.wait_group %0;" :: "n"(n))

#define LDSM_X4(R, addr) \
    asm volatile("ldmatrix.sync.aligned.m8n8.x4.shared.b16 {%0,%1,%2,%3}, [%4];" \
        : "=r"((R)[0]), "=r"((R)[1]), "=r"((R)[2]), "=r"((R)[3]) : "r"(addr))
#define LDSM_X4T(R, addr) \
    asm volatile("ldmatrix.sync.aligned.m8n8.x4.trans.shared.b16 {%0,%1,%2,%3}, [%4];" \
        : "=r"((R)[0]), "=r"((R)[1]), "=r"((R)[2]), "=r"((R)[3]) : "r"(addr))

__device__ __forceinline__ void mma16816(float* d, const uint32_t* a,
                                         uint32_t b0, uint32_t b1) {
    asm volatile(
        "mma.sync.aligned.m16n8k16.row.col.f32.bf16.bf16.f32 "
        "{%0,%1,%2,%3}, {%4,%5,%6,%7}, {%8,%9}, {%0,%1,%2,%3};"
        : "+f"(d[0]), "+f"(d[1]), "+f"(d[2]), "+f"(d[3])
        : "r"(a[0]), "r"(a[1]), "r"(a[2]), "r"(a[3]), "r"(b0), "r"(b1));
}

// pack: result = { lo = bf16(lo_f), hi = bf16(hi_f) }
__device__ __forceinline__ uint32_t pack_bf16x2(float lo_f, float hi_f) {
    uint32_t r;
    asm("cvt.rn.bf16x2.f32 %0, %1, %2;" : "=r"(r) : "f"(hi_f), "f"(lo_f));
    return r;
}

__global__ void __launch_bounds__(THREADS)
netvlad_mma(const float* __restrict__ x, const float* __restrict__ conv_w,
            const float* __restrict__ centroids, float* __restrict__ out) {
    extern __shared__ char smem[];
    const uint32_t sb = smem_u32(smem);
    const int tid  = threadIdx.x;
    const int lane = tid & 31;
    const int warp = tid >> 5;
    const int split = blockIdx.x;
    const int n     = blockIdx.y;

    if (tid < KK) ((float*)(smem + OFF_ASUM))[tid] = 0.f;

    // conv_w [64][128] -> bf16, swizzled rows
    for (int i = tid; i < KK * CC; i += THREADS) {
        int k = i >> 7, c = i & 127;
        *(uint16_t*)(smem + OFF_W + swz256(k, c * 2)) =
            __bfloat16_as_ushort(__float2bfloat16_rn(conv_w[i]));
    }

    float vacc[32];
    #pragma unroll
    for (int i = 0; i < 32; i++) vacc[i] = 0.f;
    float asum[16];
    #pragma unroll
    for (int i = 0; i < 16; i++) asum[i] = 0.f;

    const float* xb_g = x + ((size_t)n * CC) * SS + (size_t)split * SPER;
    const int mt = warp & 3;   // GEMM2 m-tile (clusters)
    const int ch = warp >> 2;  // GEMM2 n-half (channels)
    const int wp = warp * 16;  // GEMM1 pixel base

    // prologue: stage tile 0
    {
        const float* xt = xb_g;
        #pragma unroll
        for (int j = 0; j < 16; ++j) {
            int c = warp * 16 + j;
            CP_ASYNC16(sb + OFF_ST0 + c * 512 + lane * 16, xt + (size_t)c * SS + lane * 4);
        }
        CP_COMMIT();
    }

    for (int t = 0; t < NTILES; ++t) {
        const int stoff = (t & 1) ? OFF_ST1 : OFF_ST0;
        if (t + 1 < NTILES) {
            const float* xt = xb_g + (t + 1) * TP;
            const int nstoff = ((t + 1) & 1) ? OFF_ST1 : OFF_ST0;
            #pragma unroll
            for (int j = 0; j < 16; ++j) {
                int c = warp * 16 + j;
                CP_ASYNC16(sb + nstoff + c * 512 + lane * 16, xt + (size_t)c * SS + lane * 4);
            }
            CP_COMMIT();
            CP_WAIT(1);
        } else {
            CP_WAIT(0);
        }
        __syncthreads();

        // ---- convert staging fp32 [c][p] -> bf16 [p][c] swizzled ----
        #pragma unroll
        for (int j = 0; j < 8; ++j) {
            int c0 = (warp * 8 + j) * 2;
            float4 va = *(const float4*)(smem + stoff + c0 * 512 + lane * 16);
            float4 vb = *(const float4*)(smem + stoff + (c0 + 1) * 512 + lane * 16);
            float av[4] = {va.x, va.y, va.z, va.w};
            float bv[4] = {vb.x, vb.y, vb.z, vb.w};
            #pragma unroll
            for (int e = 0; e < 4; ++e) {
                int p = lane * 4 + e;
                *(uint32_t*)(smem + OFF_XB + swz256(p, c0 * 2)) = pack_bf16x2(av[e], bv[e]);
            }
        }
        __syncthreads();

        // ---- GEMM1: logits[p][k] = x · w^T ----
        float lacc[32];
        #pragma unroll
        for (int i = 0; i < 32; i++) lacc[i] = 0.f;

        #pragma unroll
        for (int ks = 0; ks < 8; ++ks) {
            uint32_t ah[4];
            {
                int arow = wp + (lane & 15);
                int abyte = ks * 32 + (lane >> 4) * 16;
                LDSM_X4(ah, sb + OFF_XB + swz256(arow, abyte));
            }
            uint32_t bh[16];
            #pragma unroll
            for (int np = 0; np < 4; ++np) {
                int brow = np * 16 + (lane & 7) + ((lane >> 4) & 1) * 8;
                int bbyte = ks * 32 + ((lane >> 3) & 1) * 16;
                LDSM_X4(bh + np * 4, sb + OFF_W + swz256(brow, bbyte));
            }
            #pragma unroll
            for (int nt = 0; nt < 8; ++nt) {
                int bi = (nt >> 1) * 4 + (nt & 1) * 2;
                mma16816(lacc + nt * 4, ah, bh[bi], bh[bi + 1]);
            }
        }

        // ---- softmax over K (quad shuffle) ----
        float m1 = -1e30f, m2 = -1e30f;
        #pragma unroll
        for (int nt = 0; nt < 8; ++nt) {
            m1 = fmaxf(m1, fmaxf(lacc[nt * 4 + 0], lacc[nt * 4 + 1]));
            m2 = fmaxf(m2, fmaxf(lacc[nt * 4 + 2], lacc[nt * 4 + 3]));
        }
        #pragma unroll
        for (int o = 1; o <= 2; o <<= 1) {
            m1 = fmaxf(m1, __shfl_xor_sync(0xFFFFFFFFu, m1, o));
            m2 = fmaxf(m2, __shfl_xor_sync(0xFFFFFFFFu, m2, o));
        }
        float s1 = 0.f, s2 = 0.f;
        #pragma unroll
        for (int nt = 0; nt < 8; ++nt) {
            float e0 = __expf(lacc[nt * 4 + 0] - m1);
            float e1 = __expf(lacc[nt * 4 + 1] - m1);
            float e2 = __expf(lacc[nt * 4 + 2] - m2);
            float e3 = __expf(lacc[nt * 4 + 3] - m2);
            lacc[nt * 4 + 0] = e0; lacc[nt * 4 + 1] = e1;
            lacc[nt * 4 + 2] = e2; lacc[nt * 4 + 3] = e3;
            s1 += e0 + e1; s2 += e2 + e3;
        }
        #pragma unroll
        for (int o = 1; o <= 2; o <<= 1) {
            s1 += __shfl_xor_sync(0xFFFFFFFFu, s1, o);
            s2 += __shfl_xor_sync(0xFFFFFFFFu, s2, o);
        }
        const float i1 = 1.f / s1, i2 = 1.f / s2;

        // ---- a -> SMEM bf16, accumulate asum ----
        {
            int p1 = wp + (lane >> 2), p2 = p1 + 8;
            #pragma unroll
            for (int nt = 0; nt < 8; ++nt) {
                float a0 = lacc[nt * 4 + 0] * i1, a1 = lacc[nt * 4 + 1] * i1;
                float a2 = lacc[nt * 4 + 2] * i2, a3 = lacc[nt * 4 + 3] * i2;
                asum[nt * 2 + 0] += a0 + a2;
                asum[nt * 2 + 1] += a1 + a3;
                int kbyte = nt * 16 + (lane & 3) * 4;
                *(uint32_t*)(smem + OFF_A + swz128(p1, kbyte)) = pack_bf16x2(a0, a1);
                *(uint32_t*)(smem + OFF_A + swz128(p2, kbyte)) = pack_bf16x2(a2, a3);
            }
        }
        __syncthreads();

        // ---- GEMM2: vlad^T[k][c] += a^T · x ----
        #pragma unroll
        for (int ps = 0; ps < 8; ++ps) {
            uint32_t aah[4];
            {
                int arow = ps * 16 + (lane & 7) + (lane >> 4) * 8;
                int abyte = mt * 32 + ((lane >> 3) & 1) * 16;
                LDSM_X4T(aah, sb + OFF_A + swz128(arow, abyte));
            }
            uint32_t bxh[16];
            #pragma unroll
            for (int np = 0; np < 4; ++np) {
                int brow = ps * 16 + (lane & 7) + ((lane >> 3) & 1) * 8;
                int bbyte = ch * 128 + np * 32 + (lane >> 4) * 16;
                LDSM_X4T(bxh + np * 4, sb + OFF_XB + swz256(brow, bbyte));
            }
            #pragma unroll
            for (int nt = 0; nt < 8; ++nt) {
                int bi = (nt >> 1) * 4 + (nt & 1) * 2;
                mma16816(vacc + nt * 4, aah, bxh[bi], bxh[bi + 1]);
            }
        }
    }

    // ---- write vlad partials [k][c] ----
    {
        float* dst = g_vlad_part + (size_t)(split * NB + n) * (KK * CC);
        int k1 = mt * 16 + (lane >> 2), k2 = k1 + 8;
        #pragma unroll
        for (int nt = 0; nt < 8; ++nt) {
            int c = ch * 64 + nt * 8 + (lane & 3) * 2;
            *(float2*)(dst + k1 * CC + c) = make_float2(vacc[nt * 4 + 0], vacc[nt * 4 + 1]);
            *(float2*)(dst + k2 * CC + c) = make_float2(vacc[nt * 4 + 2], vacc[nt * 4 + 3]);
        }
    }
    // ---- asum: warp reduce + smem atomic combine ----
    #pragma unroll
    for (int i = 0; i < 16; ++i) {
        float s = asum[i];
        s += __shfl_xor_sync(0xFFFFFFFFu, s, 4);
        s += __shfl_xor_sync(0xFFFFFFFFu, s, 8);
        s += __shfl_xor_sync(0xFFFFFFFFu, s, 16);
        asum[i] = s;
    }
    if (lane < 4) {
        float* as = (float*)(smem + OFF_ASUM);
        #pragma unroll
        for (int nt = 0; nt < 8; ++nt) {
            atomicAdd(as + nt * 8 + lane * 2 + 0, asum[nt * 2 + 0]);
            atomicAdd(as + nt * 8 + lane * 2 + 1, asum[nt * 2 + 1]);
        }
    }
    __syncthreads();
    if (tid < KK)
        g_asum_part[(size_t)(split * NB + n) * KK + tid] = ((float*)(smem + OFF_ASUM))[tid];

    // ---- signal partials ready ----
    __threadfence();
    __syncthreads();
    if (tid == 0) atomicAdd(&g_flag[n], 1u);

    if (split != 0) return;

    // ================= fused finalize (split-0 CTA) =================
    if (tid == 0) { while (atomicAdd(&g_flag[n], 0u) < 2u) { } }
    __syncthreads();
    __threadfence();

    float* v      = (float*)(smem + OFF_ST0);          // 32 KB
    float* fasum  = (float*)(smem + OFF_ST1);
    float* rowinv = (float*)(smem + OFF_ST1 + 256);
    float* wsum   = (float*)(smem + OFF_ST1 + 512);

    if (tid < KK)
        fasum[tid] = g_asum_part[(size_t)n * KK + tid] +
                     g_asum_part[(size_t)(NB + n) * KK + tid];
    __syncthreads();

    const float* p0 = g_vlad_part + (size_t)n * (KK * CC);
    const float* p1 = g_vlad_part + (size_t)(NB + n) * (KK * CC);
    for (int idx = tid; idx < KK * CC; idx += THREADS) {
        int k = idx >> 7;
        v[idx] = p0[idx] + p1[idx] - fasum[k] * centroids[idx];
    }
    __syncthreads();

    #pragma unroll
    for (int r = 0; r < 8; ++r) {
        int k = warp * 8 + r;
        const float* row = v + k * CC;
        float s = 0.f;
        #pragma unroll
        for (int c = lane; c < CC; c += 32) { float tv = row[c]; s += tv * tv; }
        #pragma unroll
        for (int o = 16; o; o >>= 1) s += __shfl_xor_sync(0xFFFFFFFFu, s, o);
        if (lane == 0) rowinv[k] = rsqrtf(s);
    }
    __syncthreads();

    float local = 0.f;
    for (int idx = tid; idx < KK * CC; idx += THREADS) {
        float tv = v[idx] * rowinv[idx >> 7];
        v[idx] = tv;
        local += tv * tv;
    }
    #pragma unroll
    for (int o = 16; o; o >>= 1) local += __shfl_xor_sync(0xFFFFFFFFu, local, o);
    if (lane == 0) wsum[warp] = local;
    __syncthreads();
    if (tid == 0) {
        float s = 0.f;
        #pragma unroll
        for (int w = 0; w < THREADS / 32; ++w) s += wsum[w];
        wsum[0] = rsqrtf(s);
    }
    __syncthreads();
    const float ginv = wsum[0];

    for (int idx = tid; idx < KK * CC; idx += THREADS)
        out[(size_t)n * (KK * CC) + idx] = v[idx] * ginv;

    __syncthreads();
    if (tid == 0) atomicExch(&g_flag[n], 0u);   // reset for next graph replay
}

extern "C" void kernel_launch(void* const* d_in, const int* in_sizes, int n_in,
                              void* d_out, int out_size) {
    const float* x         = (const float*)d_in[0];
    const float* conv_w    = (const float*)d_in[1];
    const float* centroids = (const float*)d_in[2];
    float* out = (float*)d_out;

    cudaFuncSetAttribute(netvlad_mma, cudaFuncAttributeMaxDynamicSharedMemorySize, SMEM_BYTES);
    netvlad_mma<<<dim3(SPLITS, NB), THREADS, SMEM_BYTES>>>(x, conv_w, centroids, out);
}